// round 2
// baseline (speedup 1.0000x reference)
#include <cuda_runtime.h>

typedef unsigned long long ull;

__device__ __forceinline__ ull dup2(float x) {
    ull r; asm("mov.b64 %0, {%1, %1};" : "=l"(r) : "f"(x)); return r;
}
__device__ __forceinline__ void fma2(ull& d, ull a, ull b) {
    asm("fma.rn.f32x2 %0, %1, %2, %0;" : "+l"(d) : "l"(a), "l"(b));
}
__device__ __forceinline__ void unpk(ull v, float& lo, float& hi) {
    asm("mov.b64 {%0, %1}, %2;" : "=f"(lo), "=f"(hi) : "l"(v));
}

#define BSZ 128
#define FCK 25281
#define SK  37

// scratch (no allocs allowed -> __device__ globals)
__device__ float g_y0[BSZ * 220 * 220];     // layer0 flat relu map
__device__ float g_st0[BSZ * 2];            // mean, rstd
__device__ float g_h1[BSZ * 110 * 110];     // pooled -> conv1 input
__device__ float g_y1[BSZ * 159 * 159];     // layer1 flat relu map
__device__ float g_st1[BSZ * 2];
__device__ float g_feat[BSZ * FCK];         // normalized features
__device__ float g_part[SK * BSZ * 1000];   // split-K partial logits
__device__ float g_logits[BSZ * 1000];

// ---------------------------------------------------------------------------
// conv0: local conv 3x8x8 stride 4, 16 oc, + bias + relu, scatter into 220x220
// grid (55,55), 256 threads, dynamic smem = (3072 + 128*193)*4 B
// ---------------------------------------------------------------------------
__global__ void conv0_kernel(const float* __restrict__ x,
                             const float* __restrict__ w0,
                             const float* __restrict__ b0) {
    extern __shared__ float sm[];
    float* Ws = sm;            // [192][16]  (k-major, oc fast)
    float* P  = sm + 3072;     // [128][193] patches, pitch 193 (conflict-free)
    const int i = blockIdx.x, j = blockIdx.y;
    const int t = threadIdx.x;

    const float* wloc = w0 + (i * 55 + j) * (16 * 192);
    for (int e = t; e < 3072; e += 256) {
        int oc = e / 192, k = e - oc * 192;
        Ws[k * 16 + oc] = wloc[e];
    }
    for (int e = t; e < 128 * 192; e += 256) {
        int b = e / 192, k = e - b * 192;
        int c = k >> 6, di = (k >> 3) & 7, dj = k & 7;
        P[b * 193 + k] = x[((b * 3 + c) * 224 + (i * 4 + di)) * 224 + (j * 4 + dj)];
    }
    __syncthreads();

    int b = t & 127, half = t >> 7;          // half selects oc 0..7 / 8..15
    const float* Pb = P + b * 193;
    const float* Wh = Ws + half * 8;
    ull a0 = 0, a1 = 0, a2 = 0, a3 = 0;
#pragma unroll 4
    for (int k = 0; k < 192; k++) {
        ull xp = dup2(Pb[k]);
        const ull* wp = (const ull*)(Wh + k * 16);  // 8 consecutive floats = 4 pairs
        fma2(a0, xp, wp[0]);
        fma2(a1, xp, wp[1]);
        fma2(a2, xp, wp[2]);
        fma2(a3, xp, wp[3]);
    }
    float v[8];
    unpk(a0, v[0], v[1]); unpk(a1, v[2], v[3]);
    unpk(a2, v[4], v[5]); unpk(a3, v[6], v[7]);
#pragma unroll
    for (int r = 0; r < 8; r++) {
        int oc = half * 8 + r;
        float val = fmaxf(v[r] + b0[(oc * 55 + i) * 55 + j], 0.f);
        int row = i * 4 + (oc >> 2), col = j * 4 + (oc & 3);
        g_y0[(b * 220 + row) * 220 + col] = val;
    }
}

// ---------------------------------------------------------------------------
// layernorm stats (mean, rstd) per image; which=0 -> y0 (48400), 1 -> y1 (25281)
// ---------------------------------------------------------------------------
__global__ void ln_stats_kernel(int which) {
    const float* y = which ? g_y1 : g_y0;
    float* st      = which ? g_st1 : g_st0;
    const int n    = which ? 25281 : 48400;
    int b = blockIdx.x, t = threadIdx.x;
    const float* p = y + b * n;
    float s = 0.f, ss = 0.f;
    for (int k = t; k < n; k += 256) {
        float v = p[k];
        s += v;
        ss = fmaf(v, v, ss);
    }
    __shared__ float r1[8], r2[8];
    for (int o = 16; o; o >>= 1) {
        s  += __shfl_xor_sync(0xffffffffu, s, o);
        ss += __shfl_xor_sync(0xffffffffu, ss, o);
    }
    if ((t & 31) == 0) { r1[t >> 5] = s; r2[t >> 5] = ss; }
    __syncthreads();
    if (t == 0) {
        s = 0.f; ss = 0.f;
        for (int w = 0; w < 8; w++) { s += r1[w]; ss += r2[w]; }
        float m = s / n;
        float var = ss / n - m * m;
        st[2 * b] = m;
        st[2 * b + 1] = rsqrtf(var + 1e-5f);
    }
}

// ---------------------------------------------------------------------------
// normalize (layer0) + 2x2 maxpool -> g_h1 [128][110][110]
// ---------------------------------------------------------------------------
__global__ void norm_pool_kernel(const float* __restrict__ g0,
                                 const float* __restrict__ be0) {
    int idx = blockIdx.x * 256 + threadIdx.x;
    if (idx >= BSZ * 110 * 110) return;
    int b = idx / 12100, rem = idx - b * 12100;
    int r = rem / 110, c = rem - r * 110;
    float m = g_st0[2 * b], rs = g_st0[2 * b + 1];
    float mx = -3.4e38f;
#pragma unroll
    for (int dr = 0; dr < 2; dr++)
#pragma unroll
        for (int dc = 0; dc < 2; dc++) {
            int R = 2 * r + dr, C = 2 * c + dc;
            float v = (g_y0[(b * 220 + R) * 220 + C] - m) * rs * g0[R * 220 + C]
                      + be0[R * 220 + C];
            mx = fmaxf(mx, v);
        }
    g_h1[idx] = mx;
}

// ---------------------------------------------------------------------------
// conv1: local conv 1x6x6 stride 2, 9 oc, + bias + relu, scatter into 159x159
// grid (53,53), 128 threads (one per batch image)
// ---------------------------------------------------------------------------
__global__ void conv1_kernel(const float* __restrict__ w1,
                             const float* __restrict__ b1) {
    __shared__ float Ws[324];       // [36][9]
    __shared__ float P[128 * 37];   // pitch 37 (conflict-free)
    int i = blockIdx.x, j = blockIdx.y, t = threadIdx.x;
    const float* wloc = w1 + (i * 53 + j) * 324;
    for (int e = t; e < 324; e += 128) {
        int oc = e / 36, k = e - oc * 36;
        Ws[k * 9 + oc] = wloc[e];
    }
    for (int e = t; e < 128 * 36; e += 128) {
        int b = e / 36, k = e - b * 36;
        int di = k / 6, dj = k - di * 6;
        P[b * 37 + k] = g_h1[(b * 110 + 2 * i + di) * 110 + 2 * j + dj];
    }
    __syncthreads();

    float acc[9];
#pragma unroll
    for (int oc = 0; oc < 9; oc++) acc[oc] = 0.f;
    const float* Pb = P + t * 37;
#pragma unroll 4
    for (int k = 0; k < 36; k++) {
        float xv = Pb[k];
#pragma unroll
        for (int oc = 0; oc < 9; oc++) acc[oc] = fmaf(xv, Ws[k * 9 + oc], acc[oc]);
    }
#pragma unroll
    for (int oc = 0; oc < 9; oc++) {
        float val = fmaxf(acc[oc] + b1[(oc * 53 + i) * 53 + j], 0.f);
        int row = i * 3 + oc / 3, col = j * 3 + oc % 3;
        g_y1[(t * 159 + row) * 159 + col] = val;
    }
}

// ---------------------------------------------------------------------------
// normalize layer1 -> g_feat [128][25281]
// ---------------------------------------------------------------------------
__global__ void norm1_kernel(const float* __restrict__ g1,
                             const float* __restrict__ be1) {
    int idx = blockIdx.x * 256 + threadIdx.x;
    if (idx >= BSZ * FCK) return;
    int b = idx / FCK, k = idx - b * FCK;
    float m = g_st1[2 * b], rs = g_st1[2 * b + 1];
    g_feat[idx] = (g_y1[idx] - m) * rs * g1[k] + be1[k];
}

// ---------------------------------------------------------------------------
// FC: logits_part[sk][b][n] = sum_{k in chunk} feat[b][k] * fcw[n][k]
// grid (8, SK), 256 threads; Btile=128, Ntile=128, KT=32; 8b x 8n per thread
// smem tiles [kt][128] with XOR swizzle -> conflict-free stores AND float4 loads
// ---------------------------------------------------------------------------
__global__ void fc_kernel(const float* __restrict__ fcw) {
    __shared__ float Fs[32 * 128];
    __shared__ float Wsm[32 * 128];
    int t = threadIdx.x;
    int nblk = blockIdx.x, sk = blockIdx.y;
    int kbeg = (int)((long long)FCK * sk / SK);
    int kend = (int)((long long)FCK * (sk + 1) / SK);
    int tb = t & 15, tn = t >> 4;
    int nbase = nblk * 128;

    ull acc[8][4];
#pragma unroll
    for (int r = 0; r < 8; r++)
#pragma unroll
        for (int q = 0; q < 4; q++) acc[r][q] = 0ull;

    for (int k0 = kbeg; k0 < kend; k0 += 32) {
#pragma unroll
        for (int e0 = 0; e0 < 4096; e0 += 256) {
            int e = e0 + t;
            int kt = e & 31, row = e >> 5;
            int k = k0 + kt;
            float fv = 0.f, wv = 0.f;
            if (k < kend) {
                fv = g_feat[row * FCK + k];
                int ng = nbase + row;
                if (ng < 1000) wv = fcw[ng * FCK + k];
            }
            int sw = (kt << 7) + ((((row >> 2) ^ kt) & 31) << 2) + (row & 3);
            Fs[sw] = fv;
            Wsm[sw] = wv;
        }
        __syncthreads();
#pragma unroll 2
        for (int kt = 0; kt < 32; kt++) {
            int base = kt << 7;
            ulonglong2 fA = *(const ulonglong2*)&Fs[base + ((((2 * tb)     ^ kt) & 31) << 2)];
            ulonglong2 fB = *(const ulonglong2*)&Fs[base + ((((2 * tb + 1) ^ kt) & 31) << 2)];
            float4 wA = *(const float4*)&Wsm[base + ((((2 * tn)     ^ kt) & 31) << 2)];
            float4 wB = *(const float4*)&Wsm[base + ((((2 * tn + 1) ^ kt) & 31) << 2)];
            ull wd[8] = {dup2(wA.x), dup2(wA.y), dup2(wA.z), dup2(wA.w),
                         dup2(wB.x), dup2(wB.y), dup2(wB.z), dup2(wB.w)};
#pragma unroll
            for (int r = 0; r < 8; r++) {
                fma2(acc[r][0], fA.x, wd[r]);
                fma2(acc[r][1], fA.y, wd[r]);
                fma2(acc[r][2], fB.x, wd[r]);
                fma2(acc[r][3], fB.y, wd[r]);
            }
        }
        __syncthreads();
    }

    int b0 = tb * 8;
    float* outp = g_part + sk * (BSZ * 1000);
#pragma unroll
    for (int r = 0; r < 8; r++) {
        int n = nbase + tn * 8 + r;
        if (n >= 1000) continue;
#pragma unroll
        for (int q = 0; q < 4; q++) {
            float lo, hi;
            unpk(acc[r][q], lo, hi);
            outp[(b0 + 2 * q) * 1000 + n] = lo;
            outp[(b0 + 2 * q + 1) * 1000 + n] = hi;
        }
    }
}

// ---------------------------------------------------------------------------
// reduce split-K partials (fixed order -> deterministic) + bias + softmax
// grid 128, 256 threads
// ---------------------------------------------------------------------------
__global__ void softmax_kernel(const float* __restrict__ fcb,
                               float* __restrict__ out) {
    int b = blockIdx.x, t = threadIdx.x;
    __shared__ float red[8];
    __shared__ float bc;

    for (int n = t; n < 1000; n += 256) {
        float v = fcb[n];
        for (int s = 0; s < SK; s++) v += g_part[(s * BSZ + b) * 1000 + n];
        g_logits[b * 1000 + n] = v;
    }
    __syncthreads();

    float mx = -3.4e38f;
    for (int n = t; n < 1000; n += 256) mx = fmaxf(mx, g_logits[b * 1000 + n]);
    for (int o = 16; o; o >>= 1) mx = fmaxf(mx, __shfl_xor_sync(0xffffffffu, mx, o));
    if ((t & 31) == 0) red[t >> 5] = mx;
    __syncthreads();
    if (t == 0) {
        float m = red[0];
        for (int w = 1; w < 8; w++) m = fmaxf(m, red[w]);
        bc = m;
    }
    __syncthreads();
    mx = bc;

    float s = 0.f;
    for (int n = t; n < 1000; n += 256) s += expf(g_logits[b * 1000 + n] - mx);
    for (int o = 16; o; o >>= 1) s += __shfl_xor_sync(0xffffffffu, s, o);
    __syncthreads();                 // bc read complete before reuse
    if ((t & 31) == 0) red[t >> 5] = s;
    __syncthreads();
    if (t == 0) {
        float tot = 0.f;
        for (int w = 0; w < 8; w++) tot += red[w];
        bc = 1.f / tot;
    }
    __syncthreads();
    float inv = bc;
    for (int n = t; n < 1000; n += 256)
        out[b * 1000 + n] = expf(g_logits[b * 1000 + n] - mx) * inv;
}

// ---------------------------------------------------------------------------

extern "C" void kernel_launch(void* const* d_in, const int* in_sizes, int n_in,
                              void* d_out, int out_size) {
    const float* x   = (const float*)d_in[0];
    const float* w0  = (const float*)d_in[1];
    const float* b0  = (const float*)d_in[2];
    const float* g0  = (const float*)d_in[3];
    const float* be0 = (const float*)d_in[4];
    const float* w1  = (const float*)d_in[5];
    const float* b1  = (const float*)d_in[6];
    const float* g1  = (const float*)d_in[7];
    const float* be1 = (const float*)d_in[8];
    const float* fcw = (const float*)d_in[9];
    const float* fcb = (const float*)d_in[10];
    float* out = (float*)d_out;

    const int smem0 = (3072 + 128 * 193) * (int)sizeof(float);  // 111104 B
    cudaFuncSetAttribute(conv0_kernel, cudaFuncAttributeMaxDynamicSharedMemorySize, smem0);

    conv0_kernel<<<dim3(55, 55), 256, smem0>>>(x, w0, b0);
    ln_stats_kernel<<<128, 256>>>(0);
    norm_pool_kernel<<<(BSZ * 110 * 110 + 255) / 256, 256>>>(g0, be0);
    conv1_kernel<<<dim3(53, 53), 128>>>(w1, b1);
    ln_stats_kernel<<<128, 256>>>(1);
    norm1_kernel<<<(BSZ * FCK + 255) / 256, 256>>>(g1, be1);
    fc_kernel<<<dim3(8, SK), 256>>>(fcw);
    softmax_kernel<<<128, 256>>>(fcb, out);
}

// round 3
// speedup vs baseline: 1.2596x; 1.2596x over previous
#include <cuda_runtime.h>

typedef unsigned long long ull;

__device__ __forceinline__ ull dup2(float x) {
    ull r; asm("mov.b64 %0, {%1, %1};" : "=l"(r) : "f"(x)); return r;
}
__device__ __forceinline__ void fma2(ull& d, ull a, ull b) {
    asm("fma.rn.f32x2 %0, %1, %2, %0;" : "+l"(d) : "l"(a), "l"(b));
}
__device__ __forceinline__ void unpk(ull v, float& lo, float& hi) {
    asm("mov.b64 {%0, %1}, %2;" : "=f"(lo), "=f"(hi) : "l"(v));
}

#define BSZ 128
#define FCK 25281
#define SK  37

// scratch (no allocs allowed -> __device__ globals). All intermediates are
// B-fastest ("HWB") so every gather/scatter is a coalesced 128-float row.
__device__ float g_y0[220 * 220 * BSZ];     // layer0 relu map [pos][b]
__device__ float g_p0s[3025 * BSZ];         // per-conv0-block per-b sum
__device__ float g_p0ss[3025 * BSZ];        // per-conv0-block per-b sumsq
__device__ float g_st0[BSZ * 2];            // mean, rstd
__device__ float g_h1[110 * 110 * BSZ];     // pooled [pos][b]
__device__ float g_y1[159 * 159 * BSZ];     // layer1 relu map [pos][b]
__device__ float g_p1s[2809 * BSZ];
__device__ float g_p1ss[2809 * BSZ];
__device__ float g_st1[BSZ * 2];
__device__ float g_feat[FCK * BSZ];         // normalized features [k][b]
__device__ float g_part[SK * BSZ * 1000];   // split-K partial logits
__device__ float g_logits[BSZ * 1000];

// ---------------------------------------------------------------------------
// conv0: local conv 3x8x8 stride 4, 16 oc, + bias + relu, HWB scatter,
// fused per-block LN partial sums.
// grid (55,55), 64 threads, dyn smem = (3072 + 192*128 + 512)*4 = 112640 B
// thread tile: 4 batches x 8 oc  (oc packed in f32x2) -> FMA-paced inner loop
// ---------------------------------------------------------------------------
__global__ void __launch_bounds__(64) conv0_kernel(const float* __restrict__ x,
                                                   const float* __restrict__ w0,
                                                   const float* __restrict__ b0) {
    extern __shared__ float sm[];
    float* Ws   = sm;                    // [192][16] k-major, oc fast
    float* P2   = sm + 3072;             // [192][128] k-major, b fast
    float* Ssum = sm + 3072 + 192 * 128; // [2][128]
    float* Sss  = Ssum + 256;            // [2][128]
    const int i = blockIdx.x, j = blockIdx.y;
    const int t = threadIdx.x;

    // weights -> smem transposed
    const float* wloc = w0 + (i * 55 + j) * 3072;
    for (int e = t; e < 3072; e += 64) {
        int oc = e / 192, k = e - oc * 192;
        Ws[k * 16 + oc] = wloc[e];
    }
    // patches -> smem k-major (float4 over dj quads; lanes vary b)
    for (int e = t; e < 6144; e += 64) {
        int b = e & 127, kq = e >> 7;
        int c = kq >> 4, di = (kq >> 1) & 7, djq = kq & 1;
        float4 v = *(const float4*)&x[((b * 3 + c) * 224 + (i * 4 + di)) * 224
                                      + j * 4 + djq * 4];
        int k = kq * 4;
        P2[(k + 0) * 128 + b] = v.x;
        P2[(k + 1) * 128 + b] = v.y;
        P2[(k + 2) * 128 + b] = v.z;
        P2[(k + 3) * 128 + b] = v.w;
    }
    __syncthreads();

    const int bg = t & 31, half = t >> 5;   // bg: 4-batch group; half: oc 0-7/8-15
    const float* Wh = Ws + half * 8;
    ull acc[4][4];
#pragma unroll
    for (int p = 0; p < 4; p++)
#pragma unroll
        for (int q = 0; q < 4; q++) acc[p][q] = 0ull;

#pragma unroll 2
    for (int k = 0; k < 192; k++) {
        float4 xq = *(const float4*)&P2[k * 128 + bg * 4];
        const ull* wp = (const ull*)&Wh[k * 16];
        ull w0v = wp[0], w1v = wp[1], w2v = wp[2], w3v = wp[3];
        ull x0 = dup2(xq.x), x1 = dup2(xq.y), x2 = dup2(xq.z), x3 = dup2(xq.w);
        fma2(acc[0][0], x0, w0v); fma2(acc[1][0], x0, w1v);
        fma2(acc[2][0], x0, w2v); fma2(acc[3][0], x0, w3v);
        fma2(acc[0][1], x1, w0v); fma2(acc[1][1], x1, w1v);
        fma2(acc[2][1], x1, w2v); fma2(acc[3][1], x1, w3v);
        fma2(acc[0][2], x2, w0v); fma2(acc[1][2], x2, w1v);
        fma2(acc[2][2], x2, w2v); fma2(acc[3][2], x2, w3v);
        fma2(acc[0][3], x3, w0v); fma2(acc[1][3], x3, w1v);
        fma2(acc[2][3], x3, w2v); fma2(acc[3][3], x3, w3v);
    }

    float bias[8];
#pragma unroll
    for (int r = 0; r < 8; r++) bias[r] = b0[((half * 8 + r) * 55 + i) * 55 + j];

#pragma unroll
    for (int q = 0; q < 4; q++) {
        int b = bg * 4 + q;
        float s = 0.f, ss = 0.f;
#pragma unroll
        for (int p = 0; p < 4; p++) {
            float lo, hi; unpk(acc[p][q], lo, hi);
            int oc0 = half * 8 + 2 * p, oc1 = oc0 + 1;
            float v0 = fmaxf(lo + bias[2 * p], 0.f);
            float v1 = fmaxf(hi + bias[2 * p + 1], 0.f);
            g_y0[((i * 4 + (oc0 >> 2)) * 220 + (j * 4 + (oc0 & 3))) * 128 + b] = v0;
            g_y0[((i * 4 + (oc1 >> 2)) * 220 + (j * 4 + (oc1 & 3))) * 128 + b] = v1;
            s += v0 + v1;
            ss = fmaf(v0, v0, ss);
            ss = fmaf(v1, v1, ss);
        }
        Ssum[half * 128 + b] = s;
        Sss[half * 128 + b]  = ss;
    }
    __syncthreads();
    if (t < 32) {
        int blk = blockIdx.y * 55 + blockIdx.x;
        for (int b = t; b < 128; b += 32) {
            g_p0s[blk * 128 + b]  = Ssum[b] + Ssum[128 + b];
            g_p0ss[blk * 128 + b] = Sss[b] + Sss[128 + b];
        }
    }
}

// ---------------------------------------------------------------------------
// reduce per-block LN partials -> mean, rstd. grid 128 (one block per image)
// ---------------------------------------------------------------------------
__global__ void ln2_kernel(int which) {
    const float* ps  = which ? g_p1s  : g_p0s;
    const float* pss = which ? g_p1ss : g_p0ss;
    float* st        = which ? g_st1  : g_st0;
    const int nblk   = which ? 2809 : 3025;
    const float invn = which ? (1.f / 25281.f) : (1.f / 48400.f);
    int b = blockIdx.x, t = threadIdx.x;
    float s = 0.f, ss = 0.f;
    for (int k = t; k < nblk; k += 256) {
        s  += ps[k * 128 + b];
        ss += pss[k * 128 + b];
    }
    __shared__ float r1[8], r2[8];
    for (int o = 16; o; o >>= 1) {
        s  += __shfl_xor_sync(0xffffffffu, s, o);
        ss += __shfl_xor_sync(0xffffffffu, ss, o);
    }
    if ((t & 31) == 0) { r1[t >> 5] = s; r2[t >> 5] = ss; }
    __syncthreads();
    if (t == 0) {
        s = 0.f; ss = 0.f;
        for (int w = 0; w < 8; w++) { s += r1[w]; ss += r2[w]; }
        float m = s * invn;
        float var = ss * invn - m * m;
        st[2 * b] = m;
        st[2 * b + 1] = rsqrtf(var + 1e-5f);
    }
}

// ---------------------------------------------------------------------------
// normalize (layer0) + 2x2 maxpool -> g_h1 [pos][b]  (all coalesced)
// ---------------------------------------------------------------------------
__global__ void norm_pool_kernel(const float* __restrict__ g0,
                                 const float* __restrict__ be0) {
    int idx = blockIdx.x * 256 + threadIdx.x;
    if (idx >= BSZ * 110 * 110) return;
    int b = idx & 127, pos = idx >> 7;
    int r = pos / 110, c = pos - r * 110;
    float m = g_st0[2 * b], rs = g_st0[2 * b + 1];
    float mx = -3.4e38f;
#pragma unroll
    for (int dr = 0; dr < 2; dr++)
#pragma unroll
        for (int dc = 0; dc < 2; dc++) {
            int P = (2 * r + dr) * 220 + 2 * c + dc;
            float v = (g_y0[P * 128 + b] - m) * rs * g0[P] + be0[P];
            mx = fmaxf(mx, v);
        }
    g_h1[pos * 128 + b] = mx;
}

// ---------------------------------------------------------------------------
// conv1: local conv 1x6x6 stride 2, 9 oc (packed), + bias + relu, HWB scatter,
// fused LN partials. grid (53,53), 128 threads (1 batch each)
// ---------------------------------------------------------------------------
__global__ void conv1_kernel(const float* __restrict__ w1,
                             const float* __restrict__ b1) {
    __shared__ float Ws2[36 * 10];       // [k][oc] padded to 10 (8B-aligned pairs)
    __shared__ float P2[36 * 128];       // [k][b]
    int i = blockIdx.x, j = blockIdx.y, t = threadIdx.x;
    const float* wloc = w1 + (i * 53 + j) * 324;
    for (int e = t; e < 324; e += 128) {
        int oc = e / 36, k = e - oc * 36;
        Ws2[k * 10 + oc] = wloc[e];
    }
    for (int e = t; e < 36 * 128; e += 128) {
        int b = e & 127, kk = e >> 7;
        int di = kk / 6, dj = kk - di * 6;
        P2[kk * 128 + b] = g_h1[((2 * i + di) * 110 + 2 * j + dj) * 128 + b];
    }
    __syncthreads();

    ull a[4] = {0ull, 0ull, 0ull, 0ull};
    float a8 = 0.f;
#pragma unroll 4
    for (int k = 0; k < 36; k++) {
        float xv = P2[k * 128 + t];
        ull xd = dup2(xv);
        const ull* wp = (const ull*)&Ws2[k * 10];
        fma2(a[0], xd, wp[0]);
        fma2(a[1], xd, wp[1]);
        fma2(a[2], xd, wp[2]);
        fma2(a[3], xd, wp[3]);
        a8 = fmaf(xv, Ws2[k * 10 + 8], a8);
    }
    float v[9];
    unpk(a[0], v[0], v[1]); unpk(a[1], v[2], v[3]);
    unpk(a[2], v[4], v[5]); unpk(a[3], v[6], v[7]);
    v[8] = a8;
    float s = 0.f, ss = 0.f;
#pragma unroll
    for (int oc = 0; oc < 9; oc++) {
        float val = fmaxf(v[oc] + b1[(oc * 53 + i) * 53 + j], 0.f);
        int row = i * 3 + oc / 3, col = j * 3 + oc % 3;
        g_y1[(row * 159 + col) * 128 + t] = val;
        s += val;
        ss = fmaf(val, val, ss);
    }
    int blk = blockIdx.y * 53 + blockIdx.x;
    g_p1s[blk * 128 + t]  = s;
    g_p1ss[blk * 128 + t] = ss;
}

// ---------------------------------------------------------------------------
// normalize layer1 -> g_feat [k][b]
// ---------------------------------------------------------------------------
__global__ void norm1_kernel(const float* __restrict__ g1,
                             const float* __restrict__ be1) {
    int idx = blockIdx.x * 256 + threadIdx.x;
    if (idx >= BSZ * FCK) return;
    int b = idx & 127, k = idx >> 7;
    float m = g_st1[2 * b], rs = g_st1[2 * b + 1];
    g_feat[k * 128 + b] = (g_y1[k * 128 + b] - m) * rs * g1[k] + be1[k];
}

// ---------------------------------------------------------------------------
// FC: logits_part[sk][b][n] = sum_{k in chunk} feat[k][b] * fcw[n][k]
// grid (8, SK), 256 threads; Btile=128, Ntile=128, KT=32; 8b x 8n per thread
// ---------------------------------------------------------------------------
__global__ void fc_kernel(const float* __restrict__ fcw) {
    __shared__ float Fs[32 * 128];
    __shared__ float Wsm[32 * 128];
    int t = threadIdx.x;
    int nblk = blockIdx.x, sk = blockIdx.y;
    int kbeg = (int)((long long)FCK * sk / SK);
    int kend = (int)((long long)FCK * (sk + 1) / SK);
    int tb = t & 15, tn = t >> 4;
    int nbase = nblk * 128;

    ull acc[8][4];
#pragma unroll
    for (int r = 0; r < 8; r++)
#pragma unroll
        for (int q = 0; q < 4; q++) acc[r][q] = 0ull;

    for (int k0 = kbeg; k0 < kend; k0 += 32) {
        // F tile: feat is [k][b] -> lanes vary b (coalesced)
#pragma unroll
        for (int e0 = 0; e0 < 4096; e0 += 256) {
            int e = e0 + t;
            int b = e & 127, kt = e >> 7;
            int k = k0 + kt;
            float fv = (k < kend) ? g_feat[k * 128 + b] : 0.f;
            int sw = (kt << 7) + ((((b >> 2) ^ kt) & 31) << 2) + (b & 3);
            Fs[sw] = fv;
        }
        // W tile: fcw is [n][k] -> lanes vary k (coalesced)
#pragma unroll
        for (int e0 = 0; e0 < 4096; e0 += 256) {
            int e = e0 + t;
            int kt = e & 31, row = e >> 5;
            int k = k0 + kt;
            float wv = 0.f;
            int ng = nbase + row;
            if (k < kend && ng < 1000) wv = fcw[ng * FCK + k];
            int sw = (kt << 7) + ((((row >> 2) ^ kt) & 31) << 2) + (row & 3);
            Wsm[sw] = wv;
        }
        __syncthreads();
#pragma unroll 2
        for (int kt = 0; kt < 32; kt++) {
            int base = kt << 7;
            ulonglong2 fA = *(const ulonglong2*)&Fs[base + ((((2 * tb)     ^ kt) & 31) << 2)];
            ulonglong2 fB = *(const ulonglong2*)&Fs[base + ((((2 * tb + 1) ^ kt) & 31) << 2)];
            float4 wA = *(const float4*)&Wsm[base + ((((2 * tn)     ^ kt) & 31) << 2)];
            float4 wB = *(const float4*)&Wsm[base + ((((2 * tn + 1) ^ kt) & 31) << 2)];
            ull wd[8] = {dup2(wA.x), dup2(wA.y), dup2(wA.z), dup2(wA.w),
                         dup2(wB.x), dup2(wB.y), dup2(wB.z), dup2(wB.w)};
#pragma unroll
            for (int r = 0; r < 8; r++) {
                fma2(acc[r][0], fA.x, wd[r]);
                fma2(acc[r][1], fA.y, wd[r]);
                fma2(acc[r][2], fB.x, wd[r]);
                fma2(acc[r][3], fB.y, wd[r]);
            }
        }
        __syncthreads();
    }

    int b0 = tb * 8;
    float* outp = g_part + sk * (BSZ * 1000);
#pragma unroll
    for (int r = 0; r < 8; r++) {
        int n = nbase + tn * 8 + r;
        if (n >= 1000) continue;
#pragma unroll
        for (int q = 0; q < 4; q++) {
            float lo, hi;
            unpk(acc[r][q], lo, hi);
            outp[(b0 + 2 * q) * 1000 + n] = lo;
            outp[(b0 + 2 * q + 1) * 1000 + n] = hi;
        }
    }
}

// ---------------------------------------------------------------------------
// reduce split-K partials (fixed order -> deterministic) + bias + softmax
// ---------------------------------------------------------------------------
__global__ void softmax_kernel(const float* __restrict__ fcb,
                               float* __restrict__ out) {
    int b = blockIdx.x, t = threadIdx.x;
    __shared__ float red[8];
    __shared__ float bc;

    for (int n = t; n < 1000; n += 256) {
        float v = fcb[n];
        for (int s = 0; s < SK; s++) v += g_part[(s * BSZ + b) * 1000 + n];
        g_logits[b * 1000 + n] = v;
    }
    __syncthreads();

    float mx = -3.4e38f;
    for (int n = t; n < 1000; n += 256) mx = fmaxf(mx, g_logits[b * 1000 + n]);
    for (int o = 16; o; o >>= 1) mx = fmaxf(mx, __shfl_xor_sync(0xffffffffu, mx, o));
    if ((t & 31) == 0) red[t >> 5] = mx;
    __syncthreads();
    if (t == 0) {
        float m = red[0];
        for (int w = 1; w < 8; w++) m = fmaxf(m, red[w]);
        bc = m;
    }
    __syncthreads();
    mx = bc;

    float s = 0.f;
    for (int n = t; n < 1000; n += 256) s += expf(g_logits[b * 1000 + n] - mx);
    for (int o = 16; o; o >>= 1) s += __shfl_xor_sync(0xffffffffu, s, o);
    __syncthreads();
    if ((t & 31) == 0) red[t >> 5] = s;
    __syncthreads();
    if (t == 0) {
        float tot = 0.f;
        for (int w = 0; w < 8; w++) tot += red[w];
        bc = 1.f / tot;
    }
    __syncthreads();
    float inv = bc;
    for (int n = t; n < 1000; n += 256)
        out[b * 1000 + n] = expf(g_logits[b * 1000 + n] - mx) * inv;
}

// ---------------------------------------------------------------------------

extern "C" void kernel_launch(void* const* d_in, const int* in_sizes, int n_in,
                              void* d_out, int out_size) {
    const float* x   = (const float*)d_in[0];
    const float* w0  = (const float*)d_in[1];
    const float* b0  = (const float*)d_in[2];
    const float* g0  = (const float*)d_in[3];
    const float* be0 = (const float*)d_in[4];
    const float* w1  = (const float*)d_in[5];
    const float* b1  = (const float*)d_in[6];
    const float* g1  = (const float*)d_in[7];
    const float* be1 = (const float*)d_in[8];
    const float* fcw = (const float*)d_in[9];
    const float* fcb = (const float*)d_in[10];
    float* out = (float*)d_out;

    const int smem0 = (3072 + 192 * 128 + 512) * (int)sizeof(float);  // 112640 B
    cudaFuncSetAttribute(conv0_kernel, cudaFuncAttributeMaxDynamicSharedMemorySize, smem0);

    conv0_kernel<<<dim3(55, 55), 64, smem0>>>(x, w0, b0);
    ln2_kernel<<<128, 256>>>(0);
    norm_pool_kernel<<<(BSZ * 110 * 110 + 255) / 256, 256>>>(g0, be0);
    conv1_kernel<<<dim3(53, 53), 128>>>(w1, b1);
    ln2_kernel<<<128, 256>>>(1);
    norm1_kernel<<<(BSZ * FCK + 255) / 256, 256>>>(g1, be1);
    fc_kernel<<<dim3(8, SK), 256>>>(fcw);
    softmax_kernel<<<128, 256>>>(fcb, out);
}

// round 4
// speedup vs baseline: 1.4357x; 1.1398x over previous
#include <cuda_runtime.h>

typedef unsigned long long ull;

__device__ __forceinline__ ull dup2(float x) {
    ull r; asm("mov.b64 %0, {%1, %1};" : "=l"(r) : "f"(x)); return r;
}
__device__ __forceinline__ void fma2(ull& d, ull a, ull b) {
    asm("fma.rn.f32x2 %0, %1, %2, %0;" : "+l"(d) : "l"(a), "l"(b));
}
__device__ __forceinline__ void add2(ull& d, ull a) {
    asm("add.rn.f32x2 %0, %0, %1;" : "+l"(d) : "l"(a));
}
__device__ __forceinline__ void unpk(ull v, float& lo, float& hi) {
    asm("mov.b64 {%0, %1}, %2;" : "=f"(lo), "=f"(hi) : "l"(v));
}

#define BSZ 128
#define FCK 25281
#define SK  37

// scratch (no allocs allowed -> __device__ globals). All intermediates are
// B-fastest ("HWB") so every gather/scatter is a coalesced 128-float row.
__device__ float g_y0[220 * 220 * BSZ];     // layer0 relu map [pos][b]
__device__ float g_p0s[3025 * BSZ];         // per-conv0-block per-b sum
__device__ float g_p0ss[3025 * BSZ];        // per-conv0-block per-b sumsq
__device__ float g_st0[BSZ * 2];            // mean, rstd
__device__ float g_h1[110 * 110 * BSZ];     // pooled [pos][b]
__device__ float g_y1[159 * 159 * BSZ];     // layer1 relu map [pos][b]
__device__ float g_p1s[2809 * BSZ];
__device__ float g_p1ss[2809 * BSZ];
__device__ float g_st1[BSZ * 2];
__device__ float g_feat[FCK * BSZ];         // normalized features [k][b]
__device__ float g_part[SK * BSZ * 1000];   // split-K partial logits
__device__ float g_logits[BSZ * 1000];

// ---------------------------------------------------------------------------
// conv0: local conv 3x8x8 stride 4, 16 oc, + bias + relu, HWB scatter,
// fused per-block LN partial sums.
// grid (55,55), 128 threads (4 warps -> all 4 SMSPs), split-K over 2 halves.
// dyn smem = (3072 + 192*128 + 512)*4 = 112640 B
// thread tile: 4 batches x 8 oc x 96 k  (oc packed in f32x2)
// ---------------------------------------------------------------------------
__global__ void __launch_bounds__(128) conv0_kernel(const float* __restrict__ x,
                                                    const float* __restrict__ w0,
                                                    const float* __restrict__ b0) {
    extern __shared__ float sm[];
    float* Ws   = sm;                    // [192][16] k-major, oc fast
    float* P2   = sm + 3072;             // [192][128] k-major, b fast
    float* Ssum = sm + 3072 + 192 * 128; // [2][128]
    float* Sss  = Ssum + 256;            // [2][128]
    const int i = blockIdx.x, j = blockIdx.y;
    const int t = threadIdx.x;

    // weights -> smem transposed
    const float* wloc = w0 + (i * 55 + j) * 3072;
    for (int e = t; e < 3072; e += 128) {
        int oc = e / 192, k = e - oc * 192;
        Ws[k * 16 + oc] = wloc[e];
    }
    // patches -> smem k-major (float4 over dj quads; lanes vary b)
    for (int e = t; e < 6144; e += 128) {
        int b = e & 127, kq = e >> 7;
        int c = kq >> 4, di = (kq >> 1) & 7, djq = kq & 1;
        float4 v = *(const float4*)&x[((b * 3 + c) * 224 + (i * 4 + di)) * 224
                                      + j * 4 + djq * 4];
        int k = kq * 4;
        P2[(k + 0) * 128 + b] = v.x;
        P2[(k + 1) * 128 + b] = v.y;
        P2[(k + 2) * 128 + b] = v.z;
        P2[(k + 3) * 128 + b] = v.w;
    }
    __syncthreads();

    const int bg = t & 31;               // 4-batch group
    const int half = (t >> 5) & 1;       // oc 0-7 / 8-15  (uniform per warp)
    const int kh = t >> 6;               // k half (0: k<96, 1: k>=96)
    const float* Wh = Ws + half * 8;
    ull acc[4][4];
#pragma unroll
    for (int p = 0; p < 4; p++)
#pragma unroll
        for (int q = 0; q < 4; q++) acc[p][q] = 0ull;

    const int kbase = kh * 96;
#pragma unroll 4
    for (int k = 0; k < 96; k++) {
        int kk = kbase + k;
        float4 xq = *(const float4*)&P2[kk * 128 + bg * 4];
        const ull* wp = (const ull*)&Wh[kk * 16];
        ull w0v = wp[0], w1v = wp[1], w2v = wp[2], w3v = wp[3];
        ull x0 = dup2(xq.x), x1 = dup2(xq.y), x2 = dup2(xq.z), x3 = dup2(xq.w);
        fma2(acc[0][0], x0, w0v); fma2(acc[1][0], x0, w1v);
        fma2(acc[2][0], x0, w2v); fma2(acc[3][0], x0, w3v);
        fma2(acc[0][1], x1, w0v); fma2(acc[1][1], x1, w1v);
        fma2(acc[2][1], x1, w2v); fma2(acc[3][1], x1, w3v);
        fma2(acc[0][2], x2, w0v); fma2(acc[1][2], x2, w1v);
        fma2(acc[2][2], x2, w2v); fma2(acc[3][2], x2, w3v);
        fma2(acc[0][3], x3, w0v); fma2(acc[1][3], x3, w1v);
        fma2(acc[2][3], x3, w2v); fma2(acc[3][3], x3, w3v);
    }

    // combine k-halves: kh==1 dumps accs into (dead) patch smem, kh==0 adds.
    __syncthreads();
    ull* red = (ull*)P2;                 // [16][64] (pq-major, thread fast)
    if (kh == 1) {
#pragma unroll
        for (int p = 0; p < 4; p++)
#pragma unroll
            for (int q = 0; q < 4; q++)
                red[(p * 4 + q) * 64 + (t - 64)] = acc[p][q];
    }
    __syncthreads();

    if (kh == 0) {
#pragma unroll
        for (int p = 0; p < 4; p++)
#pragma unroll
            for (int q = 0; q < 4; q++)
                add2(acc[p][q], red[(p * 4 + q) * 64 + t]);

        float bias[8];
#pragma unroll
        for (int r = 0; r < 8; r++) bias[r] = b0[((half * 8 + r) * 55 + i) * 55 + j];

#pragma unroll
        for (int q = 0; q < 4; q++) {
            int b = bg * 4 + q;
            float s = 0.f, ss = 0.f;
#pragma unroll
            for (int p = 0; p < 4; p++) {
                float lo, hi; unpk(acc[p][q], lo, hi);
                int oc0 = half * 8 + 2 * p, oc1 = oc0 + 1;
                float v0 = fmaxf(lo + bias[2 * p], 0.f);
                float v1 = fmaxf(hi + bias[2 * p + 1], 0.f);
                g_y0[((i * 4 + (oc0 >> 2)) * 220 + (j * 4 + (oc0 & 3))) * 128 + b] = v0;
                g_y0[((i * 4 + (oc1 >> 2)) * 220 + (j * 4 + (oc1 & 3))) * 128 + b] = v1;
                s += v0 + v1;
                ss = fmaf(v0, v0, ss);
                ss = fmaf(v1, v1, ss);
            }
            Ssum[half * 128 + b] = s;
            Sss[half * 128 + b]  = ss;
        }
    }
    __syncthreads();
    if (t < 32) {
        int blk = blockIdx.y * 55 + blockIdx.x;
        for (int b = t; b < 128; b += 32) {
            g_p0s[blk * 128 + b]  = Ssum[b] + Ssum[128 + b];
            g_p0ss[blk * 128 + b] = Sss[b] + Sss[128 + b];
        }
    }
}

// ---------------------------------------------------------------------------
// reduce per-block LN partials -> mean, rstd. grid 128 (one block per image)
// ---------------------------------------------------------------------------
__global__ void ln2_kernel(int which) {
    const float* ps  = which ? g_p1s  : g_p0s;
    const float* pss = which ? g_p1ss : g_p0ss;
    float* st        = which ? g_st1  : g_st0;
    const int nblk   = which ? 2809 : 3025;
    const float invn = which ? (1.f / 25281.f) : (1.f / 48400.f);
    int b = blockIdx.x, t = threadIdx.x;
    float s = 0.f, ss = 0.f;
    for (int k = t; k < nblk; k += 256) {
        s  += ps[k * 128 + b];
        ss += pss[k * 128 + b];
    }
    __shared__ float r1[8], r2[8];
    for (int o = 16; o; o >>= 1) {
        s  += __shfl_xor_sync(0xffffffffu, s, o);
        ss += __shfl_xor_sync(0xffffffffu, ss, o);
    }
    if ((t & 31) == 0) { r1[t >> 5] = s; r2[t >> 5] = ss; }
    __syncthreads();
    if (t == 0) {
        s = 0.f; ss = 0.f;
        for (int w = 0; w < 8; w++) { s += r1[w]; ss += r2[w]; }
        float m = s * invn;
        float var = ss * invn - m * m;
        st[2 * b] = m;
        st[2 * b + 1] = rsqrtf(var + 1e-5f);
    }
}

// ---------------------------------------------------------------------------
// normalize (layer0) + 2x2 maxpool -> g_h1 [pos][b]  (all coalesced)
// ---------------------------------------------------------------------------
__global__ void norm_pool_kernel(const float* __restrict__ g0,
                                 const float* __restrict__ be0) {
    int idx = blockIdx.x * 256 + threadIdx.x;
    if (idx >= BSZ * 110 * 110) return;
    int b = idx & 127, pos = idx >> 7;
    int r = pos / 110, c = pos - r * 110;
    float m = g_st0[2 * b], rs = g_st0[2 * b + 1];
    float mx = -3.4e38f;
#pragma unroll
    for (int dr = 0; dr < 2; dr++)
#pragma unroll
        for (int dc = 0; dc < 2; dc++) {
            int P = (2 * r + dr) * 220 + 2 * c + dc;
            float v = (g_y0[P * 128 + b] - m) * rs * g0[P] + be0[P];
            mx = fmaxf(mx, v);
        }
    g_h1[pos * 128 + b] = mx;
}

// ---------------------------------------------------------------------------
// conv1: local conv 1x6x6 stride 2, 9 oc, + bias + relu, HWB scatter, fused
// LN partials. grid (14,53): 4 j-locations per block, 128 threads.
// thread tile: 4 batches x 9 oc; weights pre-duplicated f32x2 in smem,
// x read directly as batch-pair ulonglong2 (no packing movs).
// ---------------------------------------------------------------------------
__global__ void __launch_bounds__(128) conv1_kernel(const float* __restrict__ w1,
                                                    const float* __restrict__ b1) {
    __shared__ __align__(16) float P[72 * 128];   // [6 rows][12 cols][128 b]
    __shared__ ull Wd[4][36][10];                  // per-loc [k][oc] dup pairs
    const int bj = blockIdx.x, i = blockIdx.y, t = threadIdx.x;

    // weights (dup-packed)
    for (int e = t; e < 4 * 324; e += 128) {
        int loc = e / 324, rem = e - loc * 324;
        int oc = rem / 36, k = rem - oc * 36;
        int j = bj * 4 + loc;
        float v = (j < 53) ? w1[(i * 53 + j) * 324 + oc * 36 + k] : 0.f;
        Wd[loc][k][oc] = dup2(v);
    }
    // shared patch union for 4 adjacent j: rows 2i..2i+5, cols 8bj..8bj+11
    for (int e = t; e < 72 * 128; e += 128) {
        int b = e & 127, pos = e >> 7;
        int di = pos / 12, dc = pos - di * 12;
        int c = 8 * bj + dc;
        P[pos * 128 + b] = (c < 110) ? g_h1[((2 * i + di) * 110 + c) * 128 + b] : 0.f;
    }
    __syncthreads();

    const int loc = t >> 5, lane = t & 31;
    const int j = bj * 4 + loc;
    const int b4 = lane * 4;
    ull acc[9][2];
#pragma unroll
    for (int oc = 0; oc < 9; oc++) { acc[oc][0] = 0ull; acc[oc][1] = 0ull; }

#pragma unroll 6
    for (int k = 0; k < 36; k++) {
        int di = k / 6, dj = k - di * 6;
        ulonglong2 xv = *(const ulonglong2*)&P[(di * 12 + 2 * loc + dj) * 128 + b4];
        const ull* wp = &Wd[loc][k][0];
#pragma unroll
        for (int oc = 0; oc < 9; oc++) {
            ull wd = wp[oc];
            fma2(acc[oc][0], xv.x, wd);
            fma2(acc[oc][1], xv.y, wd);
        }
    }

    if (j < 53) {
        float s0 = 0.f, s1 = 0.f, s2 = 0.f, s3 = 0.f;
        float q0 = 0.f, q1 = 0.f, q2 = 0.f, q3 = 0.f;
#pragma unroll
        for (int oc = 0; oc < 9; oc++) {
            float bv = b1[(oc * 53 + i) * 53 + j];
            float v0, v1, v2, v3;
            unpk(acc[oc][0], v0, v1);
            unpk(acc[oc][1], v2, v3);
            v0 = fmaxf(v0 + bv, 0.f); v1 = fmaxf(v1 + bv, 0.f);
            v2 = fmaxf(v2 + bv, 0.f); v3 = fmaxf(v3 + bv, 0.f);
            int row = i * 3 + oc / 3, col = j * 3 + oc % 3;
            float4 o; o.x = v0; o.y = v1; o.z = v2; o.w = v3;
            *(float4*)&g_y1[(row * 159 + col) * 128 + b4] = o;
            s0 += v0; s1 += v1; s2 += v2; s3 += v3;
            q0 = fmaf(v0, v0, q0); q1 = fmaf(v1, v1, q1);
            q2 = fmaf(v2, v2, q2); q3 = fmaf(v3, v3, q3);
        }
        int li = i * 53 + j;
        float4 fs; fs.x = s0; fs.y = s1; fs.z = s2; fs.w = s3;
        float4 fq; fq.x = q0; fq.y = q1; fq.z = q2; fq.w = q3;
        *(float4*)&g_p1s[li * 128 + b4]  = fs;
        *(float4*)&g_p1ss[li * 128 + b4] = fq;
    }
}

// ---------------------------------------------------------------------------
// normalize layer1 -> g_feat [k][b]
// ---------------------------------------------------------------------------
__global__ void norm1_kernel(const float* __restrict__ g1,
                             const float* __restrict__ be1) {
    int idx = blockIdx.x * 256 + threadIdx.x;
    if (idx >= BSZ * FCK) return;
    int b = idx & 127, k = idx >> 7;
    float m = g_st1[2 * b], rs = g_st1[2 * b + 1];
    g_feat[k * 128 + b] = (g_y1[k * 128 + b] - m) * rs * g1[k] + be1[k];
}

// ---------------------------------------------------------------------------
// FC: logits_part[sk][b][n] = sum_{k in chunk} feat[k][b] * fcw[n][k]
// grid (8, SK), 256 threads; Btile=128, Ntile=128, KT=32; 8b x 8n per thread
// ---------------------------------------------------------------------------
__global__ void fc_kernel(const float* __restrict__ fcw) {
    __shared__ float Fs[32 * 128];
    __shared__ float Wsm[32 * 128];
    int t = threadIdx.x;
    int nblk = blockIdx.x, sk = blockIdx.y;
    int kbeg = (int)((long long)FCK * sk / SK);
    int kend = (int)((long long)FCK * (sk + 1) / SK);
    int tb = t & 15, tn = t >> 4;
    int nbase = nblk * 128;

    ull acc[8][4];
#pragma unroll
    for (int r = 0; r < 8; r++)
#pragma unroll
        for (int q = 0; q < 4; q++) acc[r][q] = 0ull;

    for (int k0 = kbeg; k0 < kend; k0 += 32) {
        // F tile: feat is [k][b] -> lanes vary b (coalesced)
#pragma unroll
        for (int e0 = 0; e0 < 4096; e0 += 256) {
            int e = e0 + t;
            int b = e & 127, kt = e >> 7;
            int k = k0 + kt;
            float fv = (k < kend) ? g_feat[k * 128 + b] : 0.f;
            int sw = (kt << 7) + ((((b >> 2) ^ kt) & 31) << 2) + (b & 3);
            Fs[sw] = fv;
        }
        // W tile: fcw is [n][k] -> lanes vary k (coalesced)
#pragma unroll
        for (int e0 = 0; e0 < 4096; e0 += 256) {
            int e = e0 + t;
            int kt = e & 31, row = e >> 5;
            int k = k0 + kt;
            float wv = 0.f;
            int ng = nbase + row;
            if (k < kend && ng < 1000) wv = fcw[ng * FCK + k];
            int sw = (kt << 7) + ((((row >> 2) ^ kt) & 31) << 2) + (row & 3);
            Wsm[sw] = wv;
        }
        __syncthreads();
#pragma unroll 2
        for (int kt = 0; kt < 32; kt++) {
            int base = kt << 7;
            ulonglong2 fA = *(const ulonglong2*)&Fs[base + ((((2 * tb)     ^ kt) & 31) << 2)];
            ulonglong2 fB = *(const ulonglong2*)&Fs[base + ((((2 * tb + 1) ^ kt) & 31) << 2)];
            float4 wA = *(const float4*)&Wsm[base + ((((2 * tn)     ^ kt) & 31) << 2)];
            float4 wB = *(const float4*)&Wsm[base + ((((2 * tn + 1) ^ kt) & 31) << 2)];
            ull wd[8] = {dup2(wA.x), dup2(wA.y), dup2(wA.z), dup2(wA.w),
                         dup2(wB.x), dup2(wB.y), dup2(wB.z), dup2(wB.w)};
#pragma unroll
            for (int r = 0; r < 8; r++) {
                fma2(acc[r][0], fA.x, wd[r]);
                fma2(acc[r][1], fA.y, wd[r]);
                fma2(acc[r][2], fB.x, wd[r]);
                fma2(acc[r][3], fB.y, wd[r]);
            }
        }
        __syncthreads();
    }

    int b0 = tb * 8;
    float* outp = g_part + sk * (BSZ * 1000);
#pragma unroll
    for (int r = 0; r < 8; r++) {
        int n = nbase + tn * 8 + r;
        if (n >= 1000) continue;
#pragma unroll
        for (int q = 0; q < 4; q++) {
            float lo, hi;
            unpk(acc[r][q], lo, hi);
            outp[(b0 + 2 * q) * 1000 + n] = lo;
            outp[(b0 + 2 * q + 1) * 1000 + n] = hi;
        }
    }
}

// ---------------------------------------------------------------------------
// reduce split-K partials (fixed order -> deterministic) + bias + softmax
// ---------------------------------------------------------------------------
__global__ void softmax_kernel(const float* __restrict__ fcb,
                               float* __restrict__ out) {
    int b = blockIdx.x, t = threadIdx.x;
    __shared__ float red[8];
    __shared__ float bc;

    for (int n = t; n < 1000; n += 256) {
        float v = fcb[n];
        for (int s = 0; s < SK; s++) v += g_part[(s * BSZ + b) * 1000 + n];
        g_logits[b * 1000 + n] = v;
    }
    __syncthreads();

    float mx = -3.4e38f;
    for (int n = t; n < 1000; n += 256) mx = fmaxf(mx, g_logits[b * 1000 + n]);
    for (int o = 16; o; o >>= 1) mx = fmaxf(mx, __shfl_xor_sync(0xffffffffu, mx, o));
    if ((t & 31) == 0) red[t >> 5] = mx;
    __syncthreads();
    if (t == 0) {
        float m = red[0];
        for (int w = 1; w < 8; w++) m = fmaxf(m, red[w]);
        bc = m;
    }
    __syncthreads();
    mx = bc;

    float s = 0.f;
    for (int n = t; n < 1000; n += 256) s += expf(g_logits[b * 1000 + n] - mx);
    for (int o = 16; o; o >>= 1) s += __shfl_xor_sync(0xffffffffu, s, o);
    __syncthreads();
    if ((t & 31) == 0) red[t >> 5] = s;
    __syncthreads();
    if (t == 0) {
        float tot = 0.f;
        for (int w = 0; w < 8; w++) tot += red[w];
        bc = 1.f / tot;
    }
    __syncthreads();
    float inv = bc;
    for (int n = t; n < 1000; n += 256)
        out[b * 1000 + n] = expf(g_logits[b * 1000 + n] - mx) * inv;
}

// ---------------------------------------------------------------------------

extern "C" void kernel_launch(void* const* d_in, const int* in_sizes, int n_in,
                              void* d_out, int out_size) {
    const float* x   = (const float*)d_in[0];
    const float* w0  = (const float*)d_in[1];
    const float* b0  = (const float*)d_in[2];
    const float* g0  = (const float*)d_in[3];
    const float* be0 = (const float*)d_in[4];
    const float* w1  = (const float*)d_in[5];
    const float* b1  = (const float*)d_in[6];
    const float* g1  = (const float*)d_in[7];
    const float* be1 = (const float*)d_in[8];
    const float* fcw = (const float*)d_in[9];
    const float* fcb = (const float*)d_in[10];
    float* out = (float*)d_out;

    const int smem0 = (3072 + 192 * 128 + 512) * (int)sizeof(float);  // 112640 B
    cudaFuncSetAttribute(conv0_kernel, cudaFuncAttributeMaxDynamicSharedMemorySize, smem0);

    conv0_kernel<<<dim3(55, 55), 128, smem0>>>(x, w0, b0);
    ln2_kernel<<<128, 256>>>(0);
    norm_pool_kernel<<<(BSZ * 110 * 110 + 255) / 256, 256>>>(g0, be0);
    conv1_kernel<<<dim3(14, 53), 128>>>(w1, b1);
    ln2_kernel<<<128, 256>>>(1);
    norm1_kernel<<<(BSZ * FCK + 255) / 256, 256>>>(g1, be1);
    fc_kernel<<<dim3(8, SK), 256>>>(fcw);
    softmax_kernel<<<128, 256>>>(fcb, out);
}